// round 12
// baseline (speedup 1.0000x reference)
#include <cuda_runtime.h>
#include <cstdint>

// SLayer: out[b,n] = sum_p exp(-(s0*(c0-x)^2 + s1*(c1-y)^2)) * mask[b,p]
// B=64, P=16384, N=64, D=2
constexpr int B_ = 64;
constexpr int P_ = 16384;
constexpr int N_ = 64;
constexpr int SPLITS = 9;
constexpr int CHUNK = 1824;            // even -> float4-aligned pair indexing
constexpr int NPW = 4;                 // n per warp; 8 warps * 4 = 32, z covers 2 halves
constexpr int NPAIR = NPW / 2;         // 2 packed pairs

__global__ void zero_out_kernel(float* out) {
    out[blockIdx.x * blockDim.x + threadIdx.x] = 0.0f;
}

__device__ __forceinline__ float ex2_approx(float x) {
    float r;
    asm("ex2.approx.ftz.f32 %0, %1;" : "=f"(r) : "f"(x));
    return r;
}

__device__ __forceinline__ uint64_t pack2(float lo, float hi) {
    uint64_t d;
    asm("mov.b64 %0, {%1, %2};" : "=l"(d) : "f"(lo), "f"(hi));
    return d;
}

__device__ __forceinline__ void unpack2(float& lo, float& hi, uint64_t v) {
    asm("mov.b64 {%0, %1}, %2;" : "=f"(lo), "=f"(hi) : "l"(v));
}

__device__ __forceinline__ uint64_t fma2(uint64_t a, uint64_t b, uint64_t c) {
    uint64_t d;
    asm("fma.rn.f32x2 %0, %1, %2, %3;" : "=l"(d) : "l"(a), "l"(b), "l"(c));
    return d;
}

__device__ __forceinline__ uint64_t mul2(uint64_t a, uint64_t b) {
    uint64_t d;
    asm("mul.rn.f32x2 %0, %1, %2;" : "=l"(d) : "l"(a), "l"(b));
    return d;
}

__device__ __forceinline__ uint64_t add2(uint64_t a, uint64_t b) {
    uint64_t d;
    asm("add.rn.f32x2 %0, %1, %2;" : "=l"(d) : "l"(a), "l"(b));
    return d;
}

__global__ __launch_bounds__(256, 5)
void rbf_pool_kernel(const float* __restrict__ batch,
                     const float* __restrict__ mask,
                     const float* __restrict__ centers,
                     const float* __restrict__ sharp,
                     float* __restrict__ out) {
    const int b    = blockIdx.x;
    const int s    = blockIdx.y;
    const int warp = threadIdx.x >> 5;
    const int lane = threadIdx.x & 31;
    const int n0   = blockIdx.z * 32 + warp * NPW;

    // exp(-expo) = 2^(A0*dx^2 + A1*dy^2), A = -log2(e)*s, dx = x - c0.
    const float L = -1.4426950408889634f;

    uint64_t nC0[NPAIR], nC1[NPAIR], A0p[NPAIR], A1p[NPAIR], acc[NPAIR];
#pragma unroll
    for (int j = 0; j < NPAIR; j++) {
        float nc0[2], nc1[2], a0[2], a1[2];
#pragma unroll
        for (int h = 0; h < 2; h++) {
            const int n = n0 + 2 * j + h;
            nc0[h] = -centers[n * 2 + 0];
            nc1[h] = -centers[n * 2 + 1];
            a0[h]  = L * sharp[n * 2 + 0];
            a1[h]  = L * sharp[n * 2 + 1];
        }
        nC0[j] = pack2(nc0[0], nc0[1]);
        nC1[j] = pack2(nc1[0], nc1[1]);
        A0p[j] = pack2(a0[0], a0[1]);
        A1p[j] = pack2(a1[0], a1[1]);
        acc[j] = 0ull;
    }

    // Pair-indexed views: one float4 = 2 points (x0,y0,x1,y1); float2 = 2 masks.
    const float4* pts4 = reinterpret_cast<const float4*>(batch + (size_t)b * P_ * 2);
    const float2* msk2 = reinterpret_cast<const float2*>(mask + (size_t)b * P_);

    const int start = s * CHUNK;
    const int end   = (start + CHUNK < P_) ? (start + CHUNK) : P_;
    const int pair_start = start >> 1;
    const int pair_end   = end >> 1;

    int i = pair_start + lane;
    float4 f = make_float4(0.f, 0.f, 0.f, 0.f);
    float2 m = make_float2(0.f, 0.f);
    if (i < pair_end) { f = pts4[i]; m = msk2[i]; }

    while (i < pair_end) {
        // prefetch next iteration's data before touching current
        const int inext = i + 32;
        float4 fn = make_float4(0.f, 0.f, 0.f, 0.f);
        float2 mn = make_float2(0.f, 0.f);
        if (inext < pair_end) { fn = pts4[inext]; mn = msk2[inext]; }

        // point 0 broadcast pairs
        const uint64_t xb0 = pack2(f.x, f.x);
        const uint64_t yb0 = pack2(f.y, f.y);
        const uint64_t mb0 = pack2(m.x, m.x);
        // point 1 broadcast pairs
        const uint64_t xb1 = pack2(f.z, f.z);
        const uint64_t yb1 = pack2(f.w, f.w);
        const uint64_t mb1 = pack2(m.y, m.y);

#pragma unroll
        for (int j = 0; j < NPAIR; j++) {
            // point 0
            const uint64_t dx0 = add2(xb0, nC0[j]);
            const uint64_t dy0 = add2(yb0, nC1[j]);
            const uint64_t t00 = mul2(A0p[j], dx0);
            const uint64_t t10 = mul2(A1p[j], dy0);
            uint64_t e0 = mul2(t00, dx0);
            e0 = fma2(t10, dy0, e0);
            // point 1 (independent chain)
            const uint64_t dx1 = add2(xb1, nC0[j]);
            const uint64_t dy1 = add2(yb1, nC1[j]);
            const uint64_t t01 = mul2(A0p[j], dx1);
            const uint64_t t11 = mul2(A1p[j], dy1);
            uint64_t e1 = mul2(t01, dx1);
            e1 = fma2(t11, dy1, e1);

            float e0lo, e0hi, e1lo, e1hi;
            unpack2(e0lo, e0hi, e0);
            unpack2(e1lo, e1hi, e1);
            const uint64_t w0 = pack2(ex2_approx(e0lo), ex2_approx(e0hi));
            const uint64_t w1 = pack2(ex2_approx(e1lo), ex2_approx(e1hi));
            acc[j] = fma2(w0, mb0, acc[j]);
            acc[j] = fma2(w1, mb1, acc[j]);
        }

        i = inext;
        f = fn;
        m = mn;
    }

    // warp tree-reduce each accumulator pair, lane 0 commits
#pragma unroll
    for (int j = 0; j < NPAIR; j++) {
        float vlo, vhi;
        unpack2(vlo, vhi, acc[j]);
#pragma unroll
        for (int o = 16; o > 0; o >>= 1) {
            vlo += __shfl_xor_sync(0xFFFFFFFFu, vlo, o);
            vhi += __shfl_xor_sync(0xFFFFFFFFu, vhi, o);
        }
        if (lane == 0) {
            atomicAdd(&out[b * N_ + n0 + 2 * j + 0], vlo);
            atomicAdd(&out[b * N_ + n0 + 2 * j + 1], vhi);
        }
    }
}

extern "C" void kernel_launch(void* const* d_in, const int* in_sizes, int n_in,
                              void* d_out, int out_size) {
    const float* batch   = (const float*)d_in[0];  // [64,16384,2]
    const float* mask    = (const float*)d_in[1];  // [64,16384]
    const float* centers = (const float*)d_in[2];  // [64,2]
    const float* sharp   = (const float*)d_in[3];  // [64,2]
    float* out = (float*)d_out;                    // [64,64]

    zero_out_kernel<<<16, 256>>>(out);             // 4096 elems
    dim3 grid(B_, SPLITS, 2);
    rbf_pool_kernel<<<grid, 256>>>(batch, mask, centers, sharp, out);
}

// round 13
// speedup vs baseline: 1.1530x; 1.1530x over previous
#include <cuda_runtime.h>
#include <cstdint>

// SLayer: out[b,n] = sum_p exp(-(s0*(c0-x)^2 + s1*(c1-y)^2)) * mask[b,p]
// B=64, P=16384, N=64, D=2
constexpr int B_ = 64;
constexpr int P_ = 16384;
constexpr int N_ = 64;
constexpr int SPLITS = 8;
constexpr int CHUNK = P_ / SPLITS;     // 2048
constexpr int TP = 1024;               // points per SMEM tile (2 tiles per block)
constexpr int NPW = 4;                 // n per warp; 8 warps * 4 = 32, z covers 2 halves
constexpr int NPAIR = NPW / 2;         // 2 packed pairs

__global__ void zero_out_kernel(float* out) {
    out[blockIdx.x * blockDim.x + threadIdx.x] = 0.0f;
}

__device__ __forceinline__ float ex2_approx(float x) {
    float r;
    asm("ex2.approx.ftz.f32 %0, %1;" : "=f"(r) : "f"(x));
    return r;
}

__device__ __forceinline__ uint64_t pack2(float lo, float hi) {
    uint64_t d;
    asm("mov.b64 %0, {%1, %2};" : "=l"(d) : "f"(lo), "f"(hi));
    return d;
}

__device__ __forceinline__ void unpack2(float& lo, float& hi, uint64_t v) {
    asm("mov.b64 {%0, %1}, %2;" : "=f"(lo), "=f"(hi) : "l"(v));
}

__device__ __forceinline__ uint64_t fma2(uint64_t a, uint64_t b, uint64_t c) {
    uint64_t d;
    asm("fma.rn.f32x2 %0, %1, %2, %3;" : "=l"(d) : "l"(a), "l"(b), "l"(c));
    return d;
}

__device__ __forceinline__ uint64_t mul2(uint64_t a, uint64_t b) {
    uint64_t d;
    asm("mul.rn.f32x2 %0, %1, %2;" : "=l"(d) : "l"(a), "l"(b));
    return d;
}

__device__ __forceinline__ uint64_t add2(uint64_t a, uint64_t b) {
    uint64_t d;
    asm("add.rn.f32x2 %0, %1, %2;" : "=l"(d) : "l"(a), "l"(b));
    return d;
}

__device__ __forceinline__ void cp16(uint32_t dst, const void* src) {
    asm volatile("cp.async.cg.shared.global [%0], [%1], 16;" :: "r"(dst), "l"(src));
}

__global__ __launch_bounds__(256, 4)
void rbf_pool_kernel(const float* __restrict__ batch,
                     const float* __restrict__ mask,
                     const float* __restrict__ centers,
                     const float* __restrict__ sharp,
                     float* __restrict__ out) {
    __shared__ __align__(16) float2 spts[2][TP];   // 2 x 8KB
    __shared__ __align__(16) float  smsk[2][TP];   // 2 x 4KB

    const int tid  = threadIdx.x;
    const int b    = blockIdx.x;
    const int s    = blockIdx.y;
    const int warp = tid >> 5;
    const int lane = tid & 31;
    const int n0   = blockIdx.z * 32 + warp * NPW;

    // ---- stage BOTH tiles up-front (fire-and-forget; no register deps) ----
    const size_t base = (size_t)b * P_ + (size_t)s * CHUNK;
#pragma unroll
    for (int t = 0; t < 2; t++) {
        const char* psrc = (const char*)(batch) + (base + (size_t)t * TP) * 8;
        const char* msrc = (const char*)(mask)  + (base + (size_t)t * TP) * 4;
        const uint32_t pdst = (uint32_t)__cvta_generic_to_shared(&spts[t][0]);
        const uint32_t mdst = (uint32_t)__cvta_generic_to_shared(&smsk[t][0]);
        cp16(pdst + tid * 16,        psrc + tid * 16);          // 4KB
        cp16(pdst + 4096 + tid * 16, psrc + 4096 + tid * 16);   // 4KB
        cp16(mdst + tid * 16,        msrc + tid * 16);          // 4KB
        asm volatile("cp.async.commit_group;");
    }

    // ---- per-warp packed constants ----
    const float L = -1.4426950408889634f;
    uint64_t nC0[NPAIR], nC1[NPAIR], A0p[NPAIR], A1p[NPAIR], acc[NPAIR];
#pragma unroll
    for (int j = 0; j < NPAIR; j++) {
        float nc0[2], nc1[2], a0[2], a1[2];
#pragma unroll
        for (int h = 0; h < 2; h++) {
            const int n = n0 + 2 * j + h;
            nc0[h] = -centers[n * 2 + 0];
            nc1[h] = -centers[n * 2 + 1];
            a0[h]  = L * sharp[n * 2 + 0];
            a1[h]  = L * sharp[n * 2 + 1];
        }
        nC0[j] = pack2(nc0[0], nc0[1]);
        nC1[j] = pack2(nc1[0], nc1[1]);
        A0p[j] = pack2(a0[0], a0[1]);
        A1p[j] = pack2(a1[0], a1[1]);
        acc[j] = 0ull;
    }

    asm volatile("cp.async.wait_group 1;");   // tile 0 complete (this thread)
    __syncthreads();                          // all threads' tile 0 visible

#pragma unroll
    for (int t = 0; t < 2; t++) {
#pragma unroll 2
        for (int i = lane; i < TP; i += 32) {
            const float2 xy = spts[t][i];     // LDS.64, conflict-free
            const float  mm = smsk[t][i];     // LDS.32, conflict-free
            const uint64_t xb = pack2(xy.x, xy.x);
            const uint64_t yb = pack2(xy.y, xy.y);
            const uint64_t mb = pack2(mm, mm);
#pragma unroll
            for (int j = 0; j < NPAIR; j++) {
                const uint64_t dx = add2(xb, nC0[j]);
                const uint64_t dy = add2(yb, nC1[j]);
                const uint64_t t0 = mul2(A0p[j], dx);
                const uint64_t t1 = mul2(A1p[j], dy);
                uint64_t e = mul2(t0, dx);
                e = fma2(t1, dy, e);
                float elo, ehi;
                unpack2(elo, ehi, e);
                const uint64_t w = pack2(ex2_approx(elo), ex2_approx(ehi));
                acc[j] = fma2(w, mb, acc[j]);
            }
        }
        if (t == 0) {
            asm volatile("cp.async.wait_group 0;");   // tile 1 complete
            __syncthreads();
        }
    }

    // warp tree-reduce each accumulator pair, lane 0 commits
#pragma unroll
    for (int j = 0; j < NPAIR; j++) {
        float vlo, vhi;
        unpack2(vlo, vhi, acc[j]);
#pragma unroll
        for (int o = 16; o > 0; o >>= 1) {
            vlo += __shfl_xor_sync(0xFFFFFFFFu, vlo, o);
            vhi += __shfl_xor_sync(0xFFFFFFFFu, vhi, o);
        }
        if (lane == 0) {
            atomicAdd(&out[b * N_ + n0 + 2 * j + 0], vlo);
            atomicAdd(&out[b * N_ + n0 + 2 * j + 1], vhi);
        }
    }
}

extern "C" void kernel_launch(void* const* d_in, const int* in_sizes, int n_in,
                              void* d_out, int out_size) {
    const float* batch   = (const float*)d_in[0];  // [64,16384,2]
    const float* mask    = (const float*)d_in[1];  // [64,16384]
    const float* centers = (const float*)d_in[2];  // [64,2]
    const float* sharp   = (const float*)d_in[3];  // [64,2]
    float* out = (float*)d_out;                    // [64,64]

    zero_out_kernel<<<16, 256>>>(out);             // 4096 elems
    dim3 grid(B_, SPLITS, 2);
    rbf_pool_kernel<<<grid, 256>>>(batch, mask, centers, sharp, out);
}

// round 14
// speedup vs baseline: 1.1544x; 1.0013x over previous
#include <cuda_runtime.h>
#include <cstdint>

// SLayer: out[b,n] = sum_p exp(-(s0*(c0-x)^2 + s1*(c1-y)^2)) * mask[b,p]
// B=64, P=16384, N=64, D=2
constexpr int B_ = 64;
constexpr int P_ = 16384;
constexpr int N_ = 64;
constexpr int SPLITS = 8;
constexpr int CHUNK = P_ / SPLITS;     // 2048
constexpr int TP = 1024;               // points per SMEM tile (2 tiles per block)
constexpr int NPW = 4;                 // n per warp; 8 warps * 4 = 32, z covers 2 halves
constexpr int NPAIR = NPW / 2;         // 2 packed pairs

__global__ void zero_out_kernel(float* out) {
    out[blockIdx.x * blockDim.x + threadIdx.x] = 0.0f;
}

__device__ __forceinline__ float ex2_approx(float x) {
    float r;
    asm("ex2.approx.ftz.f32 %0, %1;" : "=f"(r) : "f"(x));
    return r;
}

__device__ __forceinline__ uint64_t pack2(float lo, float hi) {
    uint64_t d;
    asm("mov.b64 %0, {%1, %2};" : "=l"(d) : "f"(lo), "f"(hi));
    return d;
}

__device__ __forceinline__ void unpack2(float& lo, float& hi, uint64_t v) {
    asm("mov.b64 {%0, %1}, %2;" : "=f"(lo), "=f"(hi) : "l"(v));
}

__device__ __forceinline__ uint64_t fma2(uint64_t a, uint64_t b, uint64_t c) {
    uint64_t d;
    asm("fma.rn.f32x2 %0, %1, %2, %3;" : "=l"(d) : "l"(a), "l"(b), "l"(c));
    return d;
}

__device__ __forceinline__ uint64_t mul2(uint64_t a, uint64_t b) {
    uint64_t d;
    asm("mul.rn.f32x2 %0, %1, %2;" : "=l"(d) : "l"(a), "l"(b));
    return d;
}

__device__ __forceinline__ void cp16(uint32_t dst, const void* src) {
    asm volatile("cp.async.cg.shared.global [%0], [%1], 16;" :: "r"(dst), "l"(src));
}

__global__ __launch_bounds__(256, 5)
void rbf_pool_kernel(const float* __restrict__ batch,
                     const float* __restrict__ mask,
                     const float* __restrict__ centers,
                     const float* __restrict__ sharp,
                     float* __restrict__ out) {
    __shared__ __align__(16) float2 spts[2][TP];   // 2 x 8KB
    __shared__ __align__(16) float  smsk[2][TP];   // 2 x 4KB

    const int tid  = threadIdx.x;
    const int b    = blockIdx.x;
    const int s    = blockIdx.y;
    const int warp = tid >> 5;
    const int lane = tid & 31;
    const int n0   = blockIdx.z * 32 + warp * NPW;

    // ---- stage BOTH tiles up-front (fire-and-forget; no register deps) ----
    const size_t base = (size_t)b * P_ + (size_t)s * CHUNK;
#pragma unroll
    for (int t = 0; t < 2; t++) {
        const char* psrc = (const char*)(batch) + (base + (size_t)t * TP) * 8;
        const char* msrc = (const char*)(mask)  + (base + (size_t)t * TP) * 4;
        const uint32_t pdst = (uint32_t)__cvta_generic_to_shared(&spts[t][0]);
        const uint32_t mdst = (uint32_t)__cvta_generic_to_shared(&smsk[t][0]);
        cp16(pdst + tid * 16,        psrc + tid * 16);          // 4KB
        cp16(pdst + 4096 + tid * 16, psrc + 4096 + tid * 16);   // 4KB
        cp16(mdst + tid * 16,        msrc + tid * 16);          // 4KB
        asm volatile("cp.async.commit_group;");
    }

    // ---- per-warp packed constants (expanded quadratic, L folded) ----
    // e = A0*x^2 + A1*y^2 + Bx*x + By*y + C, exp(-expo) = 2^e
    const float L = -1.4426950408889634f;
    uint64_t A0p[NPAIR], A1p[NPAIR], Bxp[NPAIR], Byp[NPAIR], Cp[NPAIR], acc[NPAIR];
#pragma unroll
    for (int j = 0; j < NPAIR; j++) {
        float a0[2], a1[2], bx[2], by[2], cc[2];
#pragma unroll
        for (int h = 0; h < 2; h++) {
            const int n = n0 + 2 * j + h;
            const float c0 = centers[n * 2 + 0];
            const float c1 = centers[n * 2 + 1];
            const float s0 = sharp[n * 2 + 0];
            const float s1 = sharp[n * 2 + 1];
            a0[h] = L * s0;
            a1[h] = L * s1;
            bx[h] = -2.0f * L * s0 * c0;
            by[h] = -2.0f * L * s1 * c1;
            cc[h] = L * (s0 * c0 * c0 + s1 * c1 * c1);
        }
        A0p[j] = pack2(a0[0], a0[1]);
        A1p[j] = pack2(a1[0], a1[1]);
        Bxp[j] = pack2(bx[0], bx[1]);
        Byp[j] = pack2(by[0], by[1]);
        Cp[j]  = pack2(cc[0], cc[1]);
        acc[j] = 0ull;
    }

    asm volatile("cp.async.wait_group 1;");   // tile 0 complete (this thread)
    __syncthreads();                          // all threads' tile 0 visible

#pragma unroll
    for (int t = 0; t < 2; t++) {
#pragma unroll 2
        for (int i = lane; i < TP; i += 32) {
            const float2 xy = spts[t][i];     // LDS.64, conflict-free
            const float  mm = smsk[t][i];     // LDS.32, conflict-free
            const uint64_t xb  = pack2(xy.x, xy.x);
            const uint64_t yb  = pack2(xy.y, xy.y);
            const uint64_t mb  = pack2(mm, mm);
            const uint64_t x2b = mul2(xb, xb);
            const uint64_t y2b = mul2(yb, yb);
#pragma unroll
            for (int j = 0; j < NPAIR; j++) {
                uint64_t e = fma2(A0p[j], x2b, Cp[j]);
                e = fma2(A1p[j], y2b, e);
                e = fma2(Bxp[j], xb, e);
                e = fma2(Byp[j], yb, e);
                float elo, ehi;
                unpack2(elo, ehi, e);
                const uint64_t w = pack2(ex2_approx(elo), ex2_approx(ehi));
                acc[j] = fma2(w, mb, acc[j]);
            }
        }
        if (t == 0) {
            asm volatile("cp.async.wait_group 0;");   // tile 1 complete
            __syncthreads();
        }
    }

    // warp tree-reduce each accumulator pair, lane 0 commits
#pragma unroll
    for (int j = 0; j < NPAIR; j++) {
        float vlo, vhi;
        unpack2(vlo, vhi, acc[j]);
#pragma unroll
        for (int o = 16; o > 0; o >>= 1) {
            vlo += __shfl_xor_sync(0xFFFFFFFFu, vlo, o);
            vhi += __shfl_xor_sync(0xFFFFFFFFu, vhi, o);
        }
        if (lane == 0) {
            atomicAdd(&out[b * N_ + n0 + 2 * j + 0], vlo);
            atomicAdd(&out[b * N_ + n0 + 2 * j + 1], vhi);
        }
    }
}

extern "C" void kernel_launch(void* const* d_in, const int* in_sizes, int n_in,
                              void* d_out, int out_size) {
    const float* batch   = (const float*)d_in[0];  // [64,16384,2]
    const float* mask    = (const float*)d_in[1];  // [64,16384]
    const float* centers = (const float*)d_in[2];  // [64,2]
    const float* sharp   = (const float*)d_in[3];  // [64,2]
    float* out = (float*)d_out;                    // [64,64]

    zero_out_kernel<<<16, 256>>>(out);             // 4096 elems
    dim3 grid(B_, SPLITS, 2);
    rbf_pool_kernel<<<grid, 256>>>(batch, mask, centers, sharp, out);
}

// round 15
// speedup vs baseline: 1.1648x; 1.0089x over previous
#include <cuda_runtime.h>
#include <cstdint>

// SLayer: out[b,n] = sum_p exp(-(s0*(c0-x)^2 + s1*(c1-y)^2)) * mask[b,p]
// B=64, P=16384, N=64, D=2
constexpr int B_ = 64;
constexpr int P_ = 16384;
constexpr int N_ = 64;
constexpr int SPLITS = 8;
constexpr int CHUNK = P_ / SPLITS;     // 2048
constexpr int TP = 1024;               // points per SMEM tile (2 tiles per block)
constexpr int NPW = 4;                 // n per warp; 8 warps * 4 = 32, z covers 2 halves
constexpr int NPAIR = NPW / 2;         // 2 packed pairs

__global__ void zero_out_kernel(float* out) {
    out[blockIdx.x * blockDim.x + threadIdx.x] = 0.0f;
}

__device__ __forceinline__ uint64_t pack2(float lo, float hi) {
    uint64_t d;
    asm("mov.b64 %0, {%1, %2};" : "=l"(d) : "f"(lo), "f"(hi));
    return d;
}

__device__ __forceinline__ void unpack2(float& lo, float& hi, uint64_t v) {
    asm("mov.b64 {%0, %1}, %2;" : "=f"(lo), "=f"(hi) : "l"(v));
}

__device__ __forceinline__ uint64_t fma2(uint64_t a, uint64_t b, uint64_t c) {
    uint64_t d;
    asm("fma.rn.f32x2 %0, %1, %2, %3;" : "=l"(d) : "l"(a), "l"(b), "l"(c));
    return d;
}

__device__ __forceinline__ uint64_t mul2(uint64_t a, uint64_t b) {
    uint64_t d;
    asm("mul.rn.f32x2 %0, %1, %2;" : "=l"(d) : "l"(a), "l"(b));
    return d;
}

// pack two f32 exponents straight into f16x2, single MUFU ex2 for both
__device__ __forceinline__ uint32_t ex2_f16x2_from_f32(float lo, float hi) {
    uint32_t h, r;
    asm("cvt.rn.f16x2.f32 %0, %1, %2;" : "=r"(h) : "f"(hi), "f"(lo));
    asm("ex2.approx.f16x2 %0, %1;" : "=r"(r) : "r"(h));
    return r;
}

__device__ __forceinline__ uint32_t hfma2(uint32_t a, uint32_t b, uint32_t c) {
    uint32_t d;
    asm("fma.rn.f16x2 %0, %1, %2, %3;" : "=r"(d) : "r"(a), "r"(b), "r"(c));
    return d;
}

__device__ __forceinline__ uint32_t f32_to_h2(float v) {
    uint32_t r;
    asm("cvt.rn.f16x2.f32 %0, %1, %1;" : "=r"(r) : "f"(v));
    return r;
}

__device__ __forceinline__ void h2_to_f32(float& lo, float& hi, uint32_t w) {
    uint16_t h0, h1;
    asm("mov.b32 {%0, %1}, %2;" : "=h"(h0), "=h"(h1) : "r"(w));
    asm("cvt.f32.f16 %0, %1;" : "=f"(lo) : "h"(h0));
    asm("cvt.f32.f16 %0, %1;" : "=f"(hi) : "h"(h1));
}

__device__ __forceinline__ void cp16(uint32_t dst, const void* src) {
    asm volatile("cp.async.cg.shared.global [%0], [%1], 16;" :: "r"(dst), "l"(src));
}

__global__ __launch_bounds__(256, 5)
void rbf_pool_kernel(const float* __restrict__ batch,
                     const float* __restrict__ mask,
                     const float* __restrict__ centers,
                     const float* __restrict__ sharp,
                     float* __restrict__ out) {
    __shared__ __align__(16) float2 spts[2][TP];   // 2 x 8KB
    __shared__ __align__(16) float  smsk[2][TP];   // 2 x 4KB

    const int tid  = threadIdx.x;
    const int b    = blockIdx.x;
    const int s    = blockIdx.y;
    const int warp = tid >> 5;
    const int lane = tid & 31;
    const int n0   = blockIdx.z * 32 + warp * NPW;

    // ---- stage BOTH tiles up-front (fire-and-forget; no register deps) ----
    const size_t base = (size_t)b * P_ + (size_t)s * CHUNK;
#pragma unroll
    for (int t = 0; t < 2; t++) {
        const char* psrc = (const char*)(batch) + (base + (size_t)t * TP) * 8;
        const char* msrc = (const char*)(mask)  + (base + (size_t)t * TP) * 4;
        const uint32_t pdst = (uint32_t)__cvta_generic_to_shared(&spts[t][0]);
        const uint32_t mdst = (uint32_t)__cvta_generic_to_shared(&smsk[t][0]);
        cp16(pdst + tid * 16,        psrc + tid * 16);          // 4KB
        cp16(pdst + 4096 + tid * 16, psrc + 4096 + tid * 16);   // 4KB
        cp16(mdst + tid * 16,        msrc + tid * 16);          // 4KB
        asm volatile("cp.async.commit_group;");
    }

    // ---- per-warp packed constants (expanded quadratic, L folded) ----
    // e = A0*x^2 + A1*y^2 + Bx*x + By*y + C, exp(-expo) = 2^e
    const float L = -1.4426950408889634f;
    uint64_t A0p[NPAIR], A1p[NPAIR], Bxp[NPAIR], Byp[NPAIR], Cp[NPAIR];
    float facc[NPW];
#pragma unroll
    for (int j = 0; j < NPAIR; j++) {
        float a0[2], a1[2], bx[2], by[2], cc[2];
#pragma unroll
        for (int h = 0; h < 2; h++) {
            const int n = n0 + 2 * j + h;
            const float c0 = centers[n * 2 + 0];
            const float c1 = centers[n * 2 + 1];
            const float s0 = sharp[n * 2 + 0];
            const float s1 = sharp[n * 2 + 1];
            a0[h] = L * s0;
            a1[h] = L * s1;
            bx[h] = -2.0f * L * s0 * c0;
            by[h] = -2.0f * L * s1 * c1;
            cc[h] = L * (s0 * c0 * c0 + s1 * c1 * c1);
        }
        A0p[j] = pack2(a0[0], a0[1]);
        A1p[j] = pack2(a1[0], a1[1]);
        Bxp[j] = pack2(bx[0], bx[1]);
        Byp[j] = pack2(by[0], by[1]);
        Cp[j]  = pack2(cc[0], cc[1]);
        facc[2 * j] = 0.0f;
        facc[2 * j + 1] = 0.0f;
    }

    asm volatile("cp.async.wait_group 1;");   // tile 0 complete (this thread)
    __syncthreads();                          // all threads' tile 0 visible

#pragma unroll
    for (int t = 0; t < 2; t++) {
        // 32 iterations per warp per tile = 4 chunks x 8 iterations.
        // Chunk sums (<=8 in f16) flushed to f32 -> bounded rounding error.
#pragma unroll
        for (int c = 0; c < 4; c++) {
            uint32_t hacc[NPAIR];
#pragma unroll
            for (int j = 0; j < NPAIR; j++) hacc[j] = 0u;
#pragma unroll
            for (int u = 0; u < 8; u++) {
                const int i = lane + (c * 8 + u) * 32;
                const float2 xy = spts[t][i];     // LDS.64, conflict-free
                const float  mm = smsk[t][i];     // LDS.32, conflict-free
                const uint64_t xb  = pack2(xy.x, xy.x);
                const uint64_t yb  = pack2(xy.y, xy.y);
                const uint64_t x2b = mul2(xb, xb);
                const uint64_t y2b = mul2(yb, yb);
                const uint32_t mh2 = f32_to_h2(mm);
#pragma unroll
                for (int j = 0; j < NPAIR; j++) {
                    uint64_t e = fma2(A0p[j], x2b, Cp[j]);
                    e = fma2(A1p[j], y2b, e);
                    e = fma2(Bxp[j], xb, e);
                    e = fma2(Byp[j], yb, e);
                    float elo, ehi;
                    unpack2(elo, ehi, e);
                    const uint32_t w2 = ex2_f16x2_from_f32(elo, ehi); // 1 MUFU, 2 exps
                    hacc[j] = hfma2(w2, mh2, hacc[j]);
                }
            }
            // flush chunk sums to f32 accumulators
#pragma unroll
            for (int j = 0; j < NPAIR; j++) {
                float flo, fhi;
                h2_to_f32(flo, fhi, hacc[j]);
                facc[2 * j]     += flo;
                facc[2 * j + 1] += fhi;
            }
        }
        if (t == 0) {
            asm volatile("cp.async.wait_group 0;");   // tile 1 complete
            __syncthreads();
        }
    }

    // warp tree-reduce each accumulator, lane 0 commits
#pragma unroll
    for (int i = 0; i < NPW; i++) {
        float v = facc[i];
#pragma unroll
        for (int o = 16; o > 0; o >>= 1)
            v += __shfl_xor_sync(0xFFFFFFFFu, v, o);
        if (lane == 0)
            atomicAdd(&out[b * N_ + n0 + i], v);
    }
}

extern "C" void kernel_launch(void* const* d_in, const int* in_sizes, int n_in,
                              void* d_out, int out_size) {
    const float* batch   = (const float*)d_in[0];  // [64,16384,2]
    const float* mask    = (const float*)d_in[1];  // [64,16384]
    const float* centers = (const float*)d_in[2];  // [64,2]
    const float* sharp   = (const float*)d_in[3];  // [64,2]
    float* out = (float*)d_out;                    // [64,64]

    zero_out_kernel<<<16, 256>>>(out);             // 4096 elems
    dim3 grid(B_, SPLITS, 2);
    rbf_pool_kernel<<<grid, 256>>>(batch, mask, centers, sharp, out);
}